// round 8
// baseline (speedup 1.0000x reference)
#include <cuda_runtime.h>
#include <cstdint>

#define DIVUP(a,b) (((a)+(b)-1)/(b))

// ---------------- static scratch (no allocations allowed) ----------------
__device__ float g_a1[128*24*118*158];
__device__ float g_a2[128*36*57*77];
__device__ float g_a3[128*48*27*37];
__device__ float g_a4[128*64*25*35];
__device__ float g_a5[128*64*23*33];

__device__ float g_qw1[24*1*5*5];
__device__ float g_qw2[36*24*5*5];
__device__ float g_qw3[48*36*5*5];
__device__ float g_qw4[64*48*3*3];
__device__ float g_qw5[64*64*3*3];
__device__ float g_qfw1[100*48576];
__device__ float g_qfw2[50*100];
__device__ float g_qfw3[10*50];
__device__ float g_qow[10];

__device__ unsigned g_absmax[9];

#define FC1_SPLIT 32
__device__ double g_fc1part[FC1_SPLIT*128*100];
__device__ float g_f1[128*100];
__device__ float g_f2[128*50];
__device__ float g_f3[128*10];

// ---------------- weight fake-quant (exact fp32 semantics) ----------------
__global__ void k_reset_absmax() {
    if (threadIdx.x < 9) g_absmax[threadIdx.x] = 0u;
}

__global__ void k_absmax(const float* __restrict__ w, int n, int slot) {
    float m = 0.f;
    for (int i = blockIdx.x * blockDim.x + threadIdx.x; i < n; i += gridDim.x * blockDim.x)
        m = fmaxf(m, fabsf(w[i]));
#pragma unroll
    for (int off = 16; off > 0; off >>= 1)
        m = fmaxf(m, __shfl_xor_sync(0xffffffffu, m, off));
    __shared__ float sm[8];
    int lane = threadIdx.x & 31, wid = threadIdx.x >> 5;
    if (lane == 0) sm[wid] = m;
    __syncthreads();
    if (threadIdx.x == 0) {
        float mm = sm[0];
        for (int i = 1; i < (int)(blockDim.x >> 5); i++) mm = fmaxf(mm, sm[i]);
        atomicMax(&g_absmax[slot], __float_as_uint(mm)); // nonneg: uint order == float order
    }
}

__global__ void k_quantw(const float* __restrict__ w, float* __restrict__ q, int n, int slot) {
    float s = __fdiv_rn(__uint_as_float(g_absmax[slot]), 7.0f);
    for (int i = blockIdx.x * blockDim.x + threadIdx.x; i < n; i += gridDim.x * blockDim.x) {
        float r = rintf(__fdiv_rn(w[i], s));       // jnp.round = RNE
        r = fminf(fmaxf(r, -7.f), 7.f);
        q[i] = r * s;
    }
}

// fp32 activation quant: identical to reference elementwise chain
__device__ __forceinline__ float qact(float v, float as) {
    v = fmaxf(v, 0.f);
    return fminf(rintf(__fdiv_rn(v, as)), 15.f) * as;
}

// ---------------- conv1: fused sequential (kh,kw) fp32 chain ----------------
template<int CIN, int COUT, int K, int S, int OCT, int P>
__global__ void __launch_bounds__(128)
conv_seq_kernel(const float* __restrict__ x, const float* __restrict__ w,
                const float* __restrict__ bias, const float* __restrict__ act_scale,
                float* __restrict__ y, int Hin, int Win, int Hout, int Wout)
{
    constexpr int CKK = CIN * K * K;
    constexpr int WSZ = OCT * CKK;
    __shared__ float sw[WSZ];
    const int oc0 = blockIdx.y * OCT;
    const int n   = blockIdx.z;

    for (int i = threadIdx.x; i < WSZ; i += 128)
        sw[i] = w[oc0 * CKK + i];
    __syncthreads();

    const int npix = Hout * Wout;
    const int p0 = blockIdx.x * (128 * P) + threadIdx.x;

    int  xoff[P];
    bool valid[P];
#pragma unroll
    for (int j = 0; j < P; j++) {
        int p = p0 + j * 128;
        valid[j] = (p < npix);
        int pp = valid[j] ? p : 0;
        int oh = pp / Wout;
        int ow = pp - oh * Wout;
        xoff[j] = oh * S * Win + ow * S;
    }

    float acc[OCT][P];
#pragma unroll
    for (int oc = 0; oc < OCT; oc++)
#pragma unroll
        for (int j = 0; j < P; j++) acc[oc][j] = 0.f;

    const float* xn = x + (size_t)n * CIN * Hin * Win;

    for (int cin = 0; cin < CIN; cin++) {
        const float* xc = xn + cin * Hin * Win;
        const float* wc = sw + cin * (K * K);
#pragma unroll
        for (int kh = 0; kh < K; kh++) {
            const float* xr = xc + kh * Win;
#pragma unroll
            for (int kw = 0; kw < K; kw++) {
                float xv[P];
#pragma unroll
                for (int j = 0; j < P; j++)
                    xv[j] = valid[j] ? __ldg(xr + xoff[j] + kw) : 0.f;
#pragma unroll
                for (int oc = 0; oc < OCT; oc++) {
                    float wv = wc[oc * CKK + kh * K + kw];
#pragma unroll
                    for (int j = 0; j < P; j++)
                        acc[oc][j] = fmaf(xv[j], wv, acc[oc][j]);   // single fused chain
                }
            }
        }
    }

    const float as = *act_scale;
#pragma unroll
    for (int oc = 0; oc < OCT; oc++) {
        float bb = bias[oc0 + oc];
        float* yc = y + ((size_t)n * COUT + oc0 + oc) * npix;
#pragma unroll
        for (int j = 0; j < P; j++) {
            if (valid[j]) {
                float v = acc[oc][j] + bb;
                yc[p0 + j * 128] = qact(v, as);
            }
        }
    }
}

// ---------------- convs 2-5: 8-lane fp32 (proven bit-equivalent to exact) ----------------
template<int CIN, int COUT, int K, int S, int OCT, int P>
__global__ void __launch_bounds__(128)
conv_v8_kernel(const float* __restrict__ x, const float* __restrict__ w,
               const float* __restrict__ bias, const float* __restrict__ act_scale,
               float* __restrict__ y, int Hin, int Win, int Hout, int Wout)
{
    constexpr int CKK = CIN * K * K;
    constexpr int WSZ = OCT * CKK;
    constexpr int C8  = CIN / 8;
    __shared__ float sw[WSZ];   // reordered [oc][kh][kw][ci]
    const int oc0 = blockIdx.y * OCT;
    const int n   = blockIdx.z;

    for (int i = threadIdx.x; i < WSZ; i += 128) {
        int oc = i / (K * K * CIN);
        int rem = i - oc * (K * K * CIN);
        int kh = rem / (K * CIN);
        rem -= kh * (K * CIN);
        int kw = rem / CIN;
        int ci = rem - kw * CIN;
        sw[i] = w[((oc0 + oc) * CIN + ci) * (K * K) + kh * K + kw];
    }
    __syncthreads();

    const int npix = Hout * Wout;
    const int p0 = blockIdx.x * (128 * P) + threadIdx.x;

    int  xoff[P];
    bool valid[P];
#pragma unroll
    for (int j = 0; j < P; j++) {
        int p = p0 + j * 128;
        valid[j] = (p < npix);
        int pp = valid[j] ? p : 0;
        int oh = pp / Wout;
        int ow = pp - oh * Wout;
        xoff[j] = oh * S * Win + ow * S;
    }

    float s[OCT][P];
#pragma unroll
    for (int oc = 0; oc < OCT; oc++)
#pragma unroll
        for (int j = 0; j < P; j++) s[oc][j] = 0.f;

    const float* xn = x + (size_t)n * CIN * Hin * Win;
    const int HW = Hin * Win;

#pragma unroll
    for (int kh = 0; kh < K; kh++) {
#pragma unroll
        for (int kw = 0; kw < K; kw++) {
            const float* xb = xn + kh * Win + kw;
            const float* wb = sw + (kh * K + kw) * CIN;

            float v[OCT][P][8];
#pragma unroll
            for (int oc = 0; oc < OCT; oc++)
#pragma unroll
                for (int j = 0; j < P; j++) {
                    v[oc][j][0] = s[oc][j];
#pragma unroll
                    for (int l = 1; l < 8; l++) v[oc][j][l] = 0.f;
                }

#pragma unroll
            for (int c = 0; c < C8; c++) {
                float xv[P][8];
#pragma unroll
                for (int j = 0; j < P; j++)
#pragma unroll
                    for (int l = 0; l < 8; l++)
                        xv[j][l] = valid[j] ? __ldg(xb + (8 * c + l) * HW + xoff[j]) : 0.f;
#pragma unroll
                for (int oc = 0; oc < OCT; oc++) {
#pragma unroll
                    for (int l = 0; l < 8; l++) {
                        float wv = wb[oc * CKK + 8 * c + l];
#pragma unroll
                        for (int j = 0; j < P; j++)
                            v[oc][j][l] = fmaf(xv[j][l], wv, v[oc][j][l]);
                    }
                }
            }

#pragma unroll
            for (int oc = 0; oc < OCT; oc++)
#pragma unroll
                for (int j = 0; j < P; j++) {
                    float h0 = __fadd_rn(v[oc][j][0], v[oc][j][4]);
                    float h1 = __fadd_rn(v[oc][j][1], v[oc][j][5]);
                    float h2 = __fadd_rn(v[oc][j][2], v[oc][j][6]);
                    float h3 = __fadd_rn(v[oc][j][3], v[oc][j][7]);
                    s[oc][j] = __fadd_rn(__fadd_rn(h0, h2), __fadd_rn(h1, h3));
                }

#pragma unroll
            for (int ci = 8 * C8; ci < CIN; ci++) {
                float xt[P];
#pragma unroll
                for (int j = 0; j < P; j++)
                    xt[j] = valid[j] ? __ldg(xb + ci * HW + xoff[j]) : 0.f;
#pragma unroll
                for (int oc = 0; oc < OCT; oc++) {
                    float wv = wb[oc * CKK + ci];
#pragma unroll
                    for (int j = 0; j < P; j++)
                        s[oc][j] = fmaf(xt[j], wv, s[oc][j]);
                }
            }
        }
    }

    const float as = *act_scale;
#pragma unroll
    for (int oc = 0; oc < OCT; oc++) {
        float bb = bias[oc0 + oc];
        float* yc = y + ((size_t)n * COUT + oc0 + oc) * npix;
#pragma unroll
        for (int j = 0; j < P; j++) {
            if (valid[j]) {
                float v2 = s[oc][j] + bb;
                yc[p0 + j * 128] = qact(v2, as);
            }
        }
    }
}

// ---------------- FC1: fp64 split-K (flip-free zone, proven) ----------------
__global__ void __launch_bounds__(256)
k_fc1_part(const float* __restrict__ A, const float* __restrict__ Bw,
           double* __restrict__ part)
{
    __shared__ float As[32][33];
    __shared__ float Bs[32][33];
    const int tid = threadIdx.x;
    const int m0 = blockIdx.y * 32;
    const int n0 = blockIdx.x * 32;
    const int s  = blockIdx.z;
    const int KD = 48576;
    const int KT = KD / 32;
    const int TPS = DIVUP(KT, FC1_SPLIT);
    const int ty = tid >> 4, tx = tid & 15;

    double acc00 = 0.0, acc01 = 0.0, acc10 = 0.0, acc11 = 0.0;

    for (int t = 0; t < TPS; t++) {
        int k0 = (s * TPS + t) * 32;
#pragma unroll
        for (int l = 0; l < 4; l++) {
            int idx = tid + l * 256;
            int r = idx >> 5, c = idx & 31;
            float av = 0.f, bv = 0.f;
            if (k0 < KD) {
                av = A[(m0 + r) * KD + k0 + c];
                bv = (n0 + r < 100) ? Bw[(n0 + r) * KD + k0 + c] : 0.f;
            }
            As[r][c] = av;
            Bs[r][c] = bv;
        }
        __syncthreads();
#pragma unroll
        for (int kk = 0; kk < 32; kk++) {
            double a0 = (double)As[ty * 2][kk], a1 = (double)As[ty * 2 + 1][kk];
            double b0 = (double)Bs[tx * 2][kk], b1 = (double)Bs[tx * 2 + 1][kk];
            acc00 = fma(a0, b0, acc00);
            acc01 = fma(a0, b1, acc01);
            acc10 = fma(a1, b0, acc10);
            acc11 = fma(a1, b1, acc11);
        }
        __syncthreads();
    }

    int m = m0 + ty * 2, nn = n0 + tx * 2;
    if (nn     < 100) part[(s * 128 + m    ) * 100 + nn    ] = acc00;
    if (nn + 1 < 100) part[(s * 128 + m    ) * 100 + nn + 1] = acc01;
    if (nn     < 100) part[(s * 128 + m + 1) * 100 + nn    ] = acc10;
    if (nn + 1 < 100) part[(s * 128 + m + 1) * 100 + nn + 1] = acc11;
}

__global__ void k_fc1_epi(const double* __restrict__ part,
                          const float* __restrict__ bias,
                          const float* __restrict__ act_scale,
                          float* __restrict__ out)
{
    int idx = blockIdx.x * blockDim.x + threadIdx.x;
    if (idx >= 128 * 100) return;
    double v = 0.0;
    for (int s = 0; s < FC1_SPLIT; s++) v += part[s * 12800 + idx];
    int nn = idx % 100;
    float f = (float)v + bias[nn];
    out[idx] = qact(f, *act_scale);
}

// ---------------- small FC layers, fp64 (flip-free zone) ----------------
__global__ void k_fc_small(const float* __restrict__ A, const float* __restrict__ W,
                           const float* __restrict__ bias, const float* __restrict__ act_scale,
                           float* __restrict__ C, int N, int Kd)
{
    int idx = blockIdx.x * blockDim.x + threadIdx.x;
    if (idx >= 128 * N) return;
    int m = idx / N, nn = idx - m * N;
    const float* a = A + m * Kd;
    const float* w = W + nn * Kd;
    double acc = 0.0;
    for (int k = 0; k < Kd; k++) acc = fma((double)__ldg(a + k), (double)__ldg(w + k), acc);
    float f = (float)acc + bias[nn];
    C[idx] = qact(f, *act_scale);
}

__global__ void k_out(const float* __restrict__ f3, const float* __restrict__ ow_q,
                      const float* __restrict__ ob, float* __restrict__ out)
{
    int m = blockIdx.x * blockDim.x + threadIdx.x;
    if (m >= 128) return;
    double acc = 0.0;
#pragma unroll
    for (int k = 0; k < 10; k++) acc = fma((double)f3[m * 10 + k], (double)ow_q[k], acc);
    out[m] = (float)acc + ob[0];
}

// ---------------- host ----------------
extern "C" void kernel_launch(void* const* d_in, const int* in_sizes, int n_in,
                              void* d_out, int out_size)
{
    const float* x   = (const float*)d_in[0];
    const float* cw[5] = {(const float*)d_in[1], (const float*)d_in[3], (const float*)d_in[5],
                          (const float*)d_in[7], (const float*)d_in[9]};
    const float* cb[5] = {(const float*)d_in[2], (const float*)d_in[4], (const float*)d_in[6],
                          (const float*)d_in[8], (const float*)d_in[10]};
    const float* fw[3] = {(const float*)d_in[11], (const float*)d_in[13], (const float*)d_in[15]};
    const float* fb[3] = {(const float*)d_in[12], (const float*)d_in[14], (const float*)d_in[16]};
    const float* oww = (const float*)d_in[17];
    const float* obb = (const float*)d_in[18];
    const float* as  = (const float*)d_in[19];

    void *a1p, *a2p, *a3p, *a4p, *a5p;
    void *q1p, *q2p, *q3p, *q4p, *q5p, *qf1p, *qf2p, *qf3p, *qowp;
    void *partp, *f1p, *f2p, *f3p;
    cudaGetSymbolAddress(&a1p, g_a1);   cudaGetSymbolAddress(&a2p, g_a2);
    cudaGetSymbolAddress(&a3p, g_a3);   cudaGetSymbolAddress(&a4p, g_a4);
    cudaGetSymbolAddress(&a5p, g_a5);
    cudaGetSymbolAddress(&q1p, g_qw1);  cudaGetSymbolAddress(&q2p, g_qw2);
    cudaGetSymbolAddress(&q3p, g_qw3);  cudaGetSymbolAddress(&q4p, g_qw4);
    cudaGetSymbolAddress(&q5p, g_qw5);
    cudaGetSymbolAddress(&qf1p, g_qfw1); cudaGetSymbolAddress(&qf2p, g_qfw2);
    cudaGetSymbolAddress(&qf3p, g_qfw3); cudaGetSymbolAddress(&qowp, g_qow);
    cudaGetSymbolAddress(&partp, g_fc1part);
    cudaGetSymbolAddress(&f1p, g_f1);   cudaGetSymbolAddress(&f2p, g_f2);
    cudaGetSymbolAddress(&f3p, g_f3);

    float* a1 = (float*)a1p; float* a2 = (float*)a2p; float* a3 = (float*)a3p;
    float* a4 = (float*)a4p; float* a5 = (float*)a5p;

    // ---- weight quantization ----
    k_reset_absmax<<<1, 32>>>();

    const float* qsrc[9] = {cw[0], cw[1], cw[2], cw[3], cw[4], fw[0], fw[1], fw[2], oww};
    float* qdst[9] = {(float*)q1p, (float*)q2p, (float*)q3p, (float*)q4p, (float*)q5p,
                      (float*)qf1p, (float*)qf2p, (float*)qf3p, (float*)qowp};
    const int qn[9] = {24*1*5*5, 36*24*5*5, 48*36*5*5, 64*48*3*3, 64*64*3*3,
                       100*48576, 50*100, 10*50, 10};
    for (int i = 0; i < 9; i++) {
        int blocks = DIVUP(qn[i], 256); if (blocks > 512) blocks = 512;
        k_absmax<<<blocks, 256>>>(qsrc[i], qn[i], i);
    }
    for (int i = 0; i < 9; i++) {
        int blocks = DIVUP(qn[i], 256); if (blocks > 4096) blocks = 4096;
        k_quantw<<<blocks, 256>>>(qsrc[i], qdst[i], qn[i], i);
    }

    // ---- conv1: fused sequential (kh,kw) fp32 chain — the probe ----
    conv_seq_kernel<1, 24, 5, 2, 8, 4><<<dim3(DIVUP(118*158, 512), 3, 128), 128>>>(
        x, (float*)q1p, cb[0], as, a1, 240, 320, 118, 158);

    // ---- convs 2-5: 8-lane fp32 (bit-equivalent to exact) ----
    conv_v8_kernel<24, 36, 5, 2, 4, 2><<<dim3(DIVUP(57*77, 256), 9, 128), 128>>>(
        a1, (float*)q2p, cb[1], as, a2, 118, 158, 57, 77);
    conv_v8_kernel<36, 48, 5, 2, 4, 2><<<dim3(DIVUP(27*37, 256), 12, 128), 128>>>(
        a2, (float*)q3p, cb[2], as, a3, 57, 77, 27, 37);
    conv_v8_kernel<48, 64, 3, 1, 4, 2><<<dim3(DIVUP(25*35, 256), 16, 128), 128>>>(
        a3, (float*)q4p, cb[3], as, a4, 27, 37, 25, 35);
    conv_v8_kernel<64, 64, 3, 1, 4, 2><<<dim3(DIVUP(23*33, 256), 16, 128), 128>>>(
        a4, (float*)q5p, cb[4], as, a5, 25, 35, 23, 33);

    // ---- FC layers (fp64, flip-free) ----
    k_fc1_part<<<dim3(4, 4, FC1_SPLIT), 256>>>(a5, (float*)qf1p, (double*)partp);
    k_fc1_epi<<<DIVUP(128*100, 256), 256>>>((double*)partp, fb[0], as, (float*)f1p);
    k_fc_small<<<DIVUP(128*50, 128), 128>>>((float*)f1p, (float*)qf2p, fb[1], as, (float*)f2p, 50, 100);
    k_fc_small<<<DIVUP(128*10, 128), 128>>>((float*)f2p, (float*)qf3p, fb[2], as, (float*)f3p, 10, 50);
    k_out<<<1, 128>>>((float*)f3p, (float*)qowp, obb, (float*)d_out);
}

// round 9
// speedup vs baseline: 1.9949x; 1.9949x over previous
#include <cuda_runtime.h>
#include <cstdint>

#define DIVUP(a,b) (((a)+(b)-1)/(b))

// ---------------- static scratch (no allocations allowed) ----------------
// Activations in NHWC layout: [n][h][w][c]
__device__ float g_a1[128*118*158*24];
__device__ float g_a2[128*57*77*36];
__device__ float g_a3[128*27*37*48];
__device__ float g_a4[128*25*35*64];
__device__ float g_a5[128*23*33*64];

__device__ float g_qw1[24*1*5*5];
__device__ float g_qw2[36*24*5*5];
__device__ float g_qw3[48*36*5*5];
__device__ float g_qw4[64*48*3*3];
__device__ float g_qw5[64*64*3*3];
__device__ float g_qfw1t[48576*100];     // fc1 weight: quantized, NHWC-permuted, [k][n]
__device__ float g_qfw2[50*100];
__device__ float g_qfw3[10*50];
__device__ float g_qow[10];

__device__ unsigned g_absmax[9];

#define FC1_SPLIT 32
__device__ float g_fc1part[FC1_SPLIT*128*100];
__device__ float g_f1[128*100];
__device__ float g_f2[128*50];
__device__ float g_f3[128*10];

// ---------------- weight fake-quant (exact fp32 semantics) ----------------
__global__ void k_reset_absmax() {
    if (threadIdx.x < 9) g_absmax[threadIdx.x] = 0u;
}

__global__ void k_absmax(const float* __restrict__ w, int n, int slot) {
    float m = 0.f;
    for (int i = blockIdx.x * blockDim.x + threadIdx.x; i < n; i += gridDim.x * blockDim.x)
        m = fmaxf(m, fabsf(w[i]));
#pragma unroll
    for (int off = 16; off > 0; off >>= 1)
        m = fmaxf(m, __shfl_xor_sync(0xffffffffu, m, off));
    __shared__ float sm[8];
    int lane = threadIdx.x & 31, wid = threadIdx.x >> 5;
    if (lane == 0) sm[wid] = m;
    __syncthreads();
    if (threadIdx.x == 0) {
        float mm = sm[0];
        for (int i = 1; i < (int)(blockDim.x >> 5); i++) mm = fmaxf(mm, sm[i]);
        atomicMax(&g_absmax[slot], __float_as_uint(mm)); // nonneg: uint order == float order
    }
}

__device__ __forceinline__ float quant_w(float w, float s) {
    float r = rintf(__fdiv_rn(w, s));   // jnp.round = RNE
    r = fminf(fmaxf(r, -7.f), 7.f);
    return r * s;
}

__global__ void k_quantw(const float* __restrict__ w, float* __restrict__ q, int n, int slot) {
    float s = __fdiv_rn(__uint_as_float(g_absmax[slot]), 7.0f);
    for (int i = blockIdx.x * blockDim.x + threadIdx.x; i < n; i += gridDim.x * blockDim.x)
        q[i] = quant_w(w[i], s);
}

// fc1 weight: quantize + permute NCHW-flat -> NHWC-flat + transpose to [k][n]
__global__ void k_quantw_fc1t(const float* __restrict__ w, float* __restrict__ wt) {
    float s = __fdiv_rn(__uint_as_float(g_absmax[5]), 7.0f);
    const int KD = 48576;                 // 64*23*33
    for (int i = blockIdx.x * blockDim.x + threadIdx.x; i < 100 * KD; i += gridDim.x * blockDim.x) {
        int nn = i / KD, f = i - nn * KD; // f = c*759 + hw (NCHW flat)
        int c = f / 759, hw = f - c * 759;
        int g = hw * 64 + c;              // NHWC flat
        wt[g * 100 + nn] = quant_w(w[i], s);
    }
}

// fp32 activation quant: identical to reference elementwise chain
__device__ __forceinline__ float qact(float v, float as) {
    v = fmaxf(v, 0.f);
    return fminf(rintf(__fdiv_rn(v, as)), 15.f) * as;
}

// ---------------- conv1: fused sequential (kh,kw) fp32 chain; NHWC output ----------------
// Arithmetic bit-identical to the R8 passing kernel; only the store layout changed.
__global__ void __launch_bounds__(128)
conv1_nhwc(const float* __restrict__ x, const float* __restrict__ w,
           const float* __restrict__ bias, const float* __restrict__ act_scale,
           float* __restrict__ y)
{
    constexpr int K = 5, S = 2, OCT = 8, P = 4;
    constexpr int Hin = 240, Win = 320, Hout = 118, Wout = 158, COUT = 24;
    __shared__ float sw[OCT * K * K];
    const int oc0 = blockIdx.y * OCT;
    const int n   = blockIdx.z;

    for (int i = threadIdx.x; i < OCT * K * K; i += 128)
        sw[i] = w[oc0 * K * K + i];
    __syncthreads();

    const int npix = Hout * Wout;
    const int p0 = blockIdx.x * (128 * P) + threadIdx.x;

    int xoff[P];
#pragma unroll
    for (int j = 0; j < P; j++) {
        int p = p0 + j * 128;
        int pp = (p < npix) ? p : 0;
        int oh = pp / Wout, ow = pp - oh * Wout;
        xoff[j] = oh * S * Win + ow * S;
    }

    float acc[OCT][P];
#pragma unroll
    for (int oc = 0; oc < OCT; oc++)
#pragma unroll
        for (int j = 0; j < P; j++) acc[oc][j] = 0.f;

    const float* xn = x + (size_t)n * Hin * Win;

#pragma unroll
    for (int kh = 0; kh < K; kh++) {
        const float* xr = xn + kh * Win;
#pragma unroll
        for (int kw = 0; kw < K; kw++) {
            float xv[P];
#pragma unroll
            for (int j = 0; j < P; j++)
                xv[j] = __ldg(xr + xoff[j] + kw);
#pragma unroll
            for (int oc = 0; oc < OCT; oc++) {
                float wv = sw[oc * K * K + kh * K + kw];
#pragma unroll
                for (int j = 0; j < P; j++)
                    acc[oc][j] = fmaf(xv[j], wv, acc[oc][j]);   // single fused chain
            }
        }
    }

    const float as = *act_scale;
    float bb[OCT];
#pragma unroll
    for (int oc = 0; oc < OCT; oc++) bb[oc] = bias[oc0 + oc];

#pragma unroll
    for (int j = 0; j < P; j++) {
        int p = p0 + j * 128;
        if (p < npix) {
            float* yp = y + ((size_t)n * npix + p) * COUT + oc0;
            float4 o0, o1;
            o0.x = qact(acc[0][j] + bb[0], as);
            o0.y = qact(acc[1][j] + bb[1], as);
            o0.z = qact(acc[2][j] + bb[2], as);
            o0.w = qact(acc[3][j] + bb[3], as);
            o1.x = qact(acc[4][j] + bb[4], as);
            o1.y = qact(acc[5][j] + bb[5], as);
            o1.z = qact(acc[6][j] + bb[6], as);
            o1.w = qact(acc[7][j] + bb[7], as);
            *reinterpret_cast<float4*>(yp)     = o0;
            *reinterpret_cast<float4*>(yp + 4) = o1;
        }
    }
}

// ---------------- convs 2-5: NHWC, 8-lane v8 DAG (bit-identical arithmetic) ----------------
// Same per-output reduction DAG as the R8 passing conv_v8_kernel: per (kh,kw),
// 8 fp32 lane accumulators over ci (lane = ci%8, running sum folded into lane 0),
// IC2 (l,l+4) combine + shuffle-halves tree, sequential scalar tail for ci%8.
// NHWC layout turns lane loads into 2x LDG.128 and weight reads into 2x LDS.128.
template<int CIN, int COUT, int K, int S, int P>
__global__ void __launch_bounds__(128)
conv_v8_nhwc(const float* __restrict__ x, const float* __restrict__ w,
             const float* __restrict__ bias, const float* __restrict__ act_scale,
             float* __restrict__ y, int Hin, int Win, int Hout, int Wout)
{
    constexpr int OCT = 4;
    constexpr int CKK = CIN * K * K;
    constexpr int WSZ = OCT * CKK;
    constexpr int C8  = CIN / 8;
    __shared__ __align__(16) float sw[WSZ];   // [oc][kh][kw][ci]
    const int oc0 = blockIdx.y * OCT;
    const int n   = blockIdx.z;

    for (int i = threadIdx.x; i < WSZ; i += 128) {
        int oc = i / CKK;
        int rem = i - oc * CKK;
        int kh = rem / (K * CIN);
        rem -= kh * (K * CIN);
        int kw = rem / CIN;
        int ci = rem - kw * CIN;
        sw[i] = w[((oc0 + oc) * CIN + ci) * (K * K) + kh * K + kw];
    }
    __syncthreads();

    const int npix = Hout * Wout;
    const int p0 = blockIdx.x * (128 * P) + threadIdx.x;

    int xbase[P];
#pragma unroll
    for (int j = 0; j < P; j++) {
        int p = p0 + j * 128;
        int pp = (p < npix) ? p : 0;
        int oh = pp / Wout, ow = pp - oh * Wout;
        xbase[j] = (oh * S * Win + ow * S) * CIN;
    }

    float s[OCT][P];
#pragma unroll
    for (int oc = 0; oc < OCT; oc++)
#pragma unroll
        for (int j = 0; j < P; j++) s[oc][j] = 0.f;

    const float* xn = x + (size_t)n * Hin * Win * CIN;

#pragma unroll
    for (int kh = 0; kh < K; kh++) {
#pragma unroll
        for (int kw = 0; kw < K; kw++) {
            const int off = (kh * Win + kw) * CIN;
            const int woff = (kh * K + kw) * CIN;

            float v[OCT][P][8];
#pragma unroll
            for (int oc = 0; oc < OCT; oc++)
#pragma unroll
                for (int j = 0; j < P; j++) {
                    v[oc][j][0] = s[oc][j];
#pragma unroll
                    for (int l = 1; l < 8; l++) v[oc][j][l] = 0.f;
                }

#pragma unroll
            for (int c = 0; c < C8; c++) {
                float4 xa[P], xb[P];
#pragma unroll
                for (int j = 0; j < P; j++) {
                    const float4* xp = reinterpret_cast<const float4*>(xn + xbase[j] + off);
                    xa[j] = __ldg(xp + 2 * c);
                    xb[j] = __ldg(xp + 2 * c + 1);
                }
#pragma unroll
                for (int oc = 0; oc < OCT; oc++) {
                    const float4* wp = reinterpret_cast<const float4*>(sw + oc * CKK + woff);
                    float4 wa = wp[2 * c], wb = wp[2 * c + 1];
#pragma unroll
                    for (int j = 0; j < P; j++) {
                        v[oc][j][0] = fmaf(xa[j].x, wa.x, v[oc][j][0]);
                        v[oc][j][1] = fmaf(xa[j].y, wa.y, v[oc][j][1]);
                        v[oc][j][2] = fmaf(xa[j].z, wa.z, v[oc][j][2]);
                        v[oc][j][3] = fmaf(xa[j].w, wa.w, v[oc][j][3]);
                        v[oc][j][4] = fmaf(xb[j].x, wb.x, v[oc][j][4]);
                        v[oc][j][5] = fmaf(xb[j].y, wb.y, v[oc][j][5]);
                        v[oc][j][6] = fmaf(xb[j].z, wb.z, v[oc][j][6]);
                        v[oc][j][7] = fmaf(xb[j].w, wb.w, v[oc][j][7]);
                    }
                }
            }

            // reduce: IC2 combine (l, l+4) then shuffle-halves tree
#pragma unroll
            for (int oc = 0; oc < OCT; oc++)
#pragma unroll
                for (int j = 0; j < P; j++) {
                    float h0 = __fadd_rn(v[oc][j][0], v[oc][j][4]);
                    float h1 = __fadd_rn(v[oc][j][1], v[oc][j][5]);
                    float h2 = __fadd_rn(v[oc][j][2], v[oc][j][6]);
                    float h3 = __fadd_rn(v[oc][j][3], v[oc][j][7]);
                    s[oc][j] = __fadd_rn(__fadd_rn(h0, h2), __fadd_rn(h1, h3));
                }

            // scalar tail (ci = 8*C8 .. CIN-1), sequential
#pragma unroll
            for (int ci = 8 * C8; ci < CIN; ci++) {
                float xt[P];
#pragma unroll
                for (int j = 0; j < P; j++)
                    xt[j] = __ldg(xn + xbase[j] + off + ci);
#pragma unroll
                for (int oc = 0; oc < OCT; oc++) {
                    float wv = sw[oc * CKK + woff + ci];
#pragma unroll
                    for (int j = 0; j < P; j++)
                        s[oc][j] = fmaf(xt[j], wv, s[oc][j]);
                }
            }
        }
    }

    const float as = *act_scale;
    float bb[OCT];
#pragma unroll
    for (int oc = 0; oc < OCT; oc++) bb[oc] = bias[oc0 + oc];

#pragma unroll
    for (int j = 0; j < P; j++) {
        int p = p0 + j * 128;
        if (p < npix) {
            float4 o;
            o.x = qact(s[0][j] + bb[0], as);
            o.y = qact(s[1][j] + bb[1], as);
            o.z = qact(s[2][j] + bb[2], as);
            o.w = qact(s[3][j] + bb[3], as);
            *reinterpret_cast<float4*>(y + ((size_t)n * npix + p) * COUT + oc0) = o;
        }
    }
}

// ---------------- FC1: fp32 split-K (FC layers proven flip-free) ----------------
__global__ void __launch_bounds__(256)
k_fc1_part(const float* __restrict__ A, const float* __restrict__ Wt,
           float* __restrict__ part)
{
    constexpr int KD = 48576;
    constexpr int LEN = KD / FC1_SPLIT;   // 1518
    __shared__ float sA[2][LEN];
    const int tid = threadIdx.x;
    const int m0  = blockIdx.x * 2;
    const int s   = blockIdx.y;
    const int k0  = s * LEN;

    for (int i = tid; i < 2 * LEN; i += 256) {
        int r = i / LEN, k = i - r * LEN;
        sA[r][k] = A[(size_t)(m0 + r) * KD + k0 + k];
    }
    __syncthreads();

    if (tid < 200) {
        int ml = tid / 100, nn = tid - ml * 100;
        const float* wp = Wt + (size_t)k0 * 100 + nn;
        float acc = 0.f;
#pragma unroll 6
        for (int k = 0; k < LEN; k++)
            acc = fmaf(sA[ml][k], __ldg(wp + (size_t)k * 100), acc);
        part[(s * 128 + m0 + ml) * 100 + nn] = acc;
    }
}

__global__ void k_fc1_epi(const float* __restrict__ part,
                          const float* __restrict__ bias,
                          const float* __restrict__ act_scale,
                          float* __restrict__ out)
{
    int idx = blockIdx.x * blockDim.x + threadIdx.x;
    if (idx >= 128 * 100) return;
    float v = 0.f;
    for (int s = 0; s < FC1_SPLIT; s++) v += part[s * 12800 + idx];  // fixed order
    int nn = idx % 100;
    float f = v + bias[nn];
    out[idx] = qact(f, *act_scale);
}

// ---------------- small FC layers, fp64 (tiny; keep exact) ----------------
__global__ void k_fc_small(const float* __restrict__ A, const float* __restrict__ W,
                           const float* __restrict__ bias, const float* __restrict__ act_scale,
                           float* __restrict__ C, int N, int Kd)
{
    int idx = blockIdx.x * blockDim.x + threadIdx.x;
    if (idx >= 128 * N) return;
    int m = idx / N, nn = idx - m * N;
    const float* a = A + m * Kd;
    const float* w = W + nn * Kd;
    double acc = 0.0;
    for (int k = 0; k < Kd; k++) acc = fma((double)__ldg(a + k), (double)__ldg(w + k), acc);
    float f = (float)acc + bias[nn];
    C[idx] = qact(f, *act_scale);
}

__global__ void k_out(const float* __restrict__ f3, const float* __restrict__ ow_q,
                      const float* __restrict__ ob, float* __restrict__ out)
{
    int m = blockIdx.x * blockDim.x + threadIdx.x;
    if (m >= 128) return;
    double acc = 0.0;
#pragma unroll
    for (int k = 0; k < 10; k++) acc = fma((double)f3[m * 10 + k], (double)ow_q[k], acc);
    out[m] = (float)acc + ob[0];
}

// ---------------- host ----------------
extern "C" void kernel_launch(void* const* d_in, const int* in_sizes, int n_in,
                              void* d_out, int out_size)
{
    const float* x   = (const float*)d_in[0];
    const float* cw[5] = {(const float*)d_in[1], (const float*)d_in[3], (const float*)d_in[5],
                          (const float*)d_in[7], (const float*)d_in[9]};
    const float* cb[5] = {(const float*)d_in[2], (const float*)d_in[4], (const float*)d_in[6],
                          (const float*)d_in[8], (const float*)d_in[10]};
    const float* fw[3] = {(const float*)d_in[11], (const float*)d_in[13], (const float*)d_in[15]};
    const float* fb[3] = {(const float*)d_in[12], (const float*)d_in[14], (const float*)d_in[16]};
    const float* oww = (const float*)d_in[17];
    const float* obb = (const float*)d_in[18];
    const float* as  = (const float*)d_in[19];

    void *a1p, *a2p, *a3p, *a4p, *a5p;
    void *q1p, *q2p, *q3p, *q4p, *q5p, *qf1tp, *qf2p, *qf3p, *qowp;
    void *partp, *f1p, *f2p, *f3p;
    cudaGetSymbolAddress(&a1p, g_a1);   cudaGetSymbolAddress(&a2p, g_a2);
    cudaGetSymbolAddress(&a3p, g_a3);   cudaGetSymbolAddress(&a4p, g_a4);
    cudaGetSymbolAddress(&a5p, g_a5);
    cudaGetSymbolAddress(&q1p, g_qw1);  cudaGetSymbolAddress(&q2p, g_qw2);
    cudaGetSymbolAddress(&q3p, g_qw3);  cudaGetSymbolAddress(&q4p, g_qw4);
    cudaGetSymbolAddress(&q5p, g_qw5);
    cudaGetSymbolAddress(&qf1tp, g_qfw1t); cudaGetSymbolAddress(&qf2p, g_qfw2);
    cudaGetSymbolAddress(&qf3p, g_qfw3);   cudaGetSymbolAddress(&qowp, g_qow);
    cudaGetSymbolAddress(&partp, g_fc1part);
    cudaGetSymbolAddress(&f1p, g_f1);   cudaGetSymbolAddress(&f2p, g_f2);
    cudaGetSymbolAddress(&f3p, g_f3);

    float* a1 = (float*)a1p; float* a2 = (float*)a2p; float* a3 = (float*)a3p;
    float* a4 = (float*)a4p; float* a5 = (float*)a5p;

    // ---- weight quantization ----
    k_reset_absmax<<<1, 32>>>();

    const float* qsrc[9] = {cw[0], cw[1], cw[2], cw[3], cw[4], fw[0], fw[1], fw[2], oww};
    const int qn[9] = {24*1*5*5, 36*24*5*5, 48*36*5*5, 64*48*3*3, 64*64*3*3,
                       100*48576, 50*100, 10*50, 10};
    for (int i = 0; i < 9; i++) {
        int blocks = DIVUP(qn[i], 256); if (blocks > 512) blocks = 512;
        k_absmax<<<blocks, 256>>>(qsrc[i], qn[i], i);
    }
    k_quantw<<<DIVUP(qn[0],256), 256>>>(qsrc[0], (float*)q1p, qn[0], 0);
    k_quantw<<<DIVUP(qn[1],256), 256>>>(qsrc[1], (float*)q2p, qn[1], 1);
    k_quantw<<<DIVUP(qn[2],256), 256>>>(qsrc[2], (float*)q3p, qn[2], 2);
    k_quantw<<<DIVUP(qn[3],256), 256>>>(qsrc[3], (float*)q4p, qn[3], 3);
    k_quantw<<<DIVUP(qn[4],256), 256>>>(qsrc[4], (float*)q5p, qn[4], 4);
    k_quantw_fc1t<<<4096, 256>>>(qsrc[5], (float*)qf1tp);
    k_quantw<<<DIVUP(qn[6],256), 256>>>(qsrc[6], (float*)qf2p, qn[6], 6);
    k_quantw<<<DIVUP(qn[7],256), 256>>>(qsrc[7], (float*)qf3p, qn[7], 7);
    k_quantw<<<1, 32>>>(qsrc[8], (float*)qowp, qn[8], 8);

    // ---- conv1: fused sequential chain, NHWC out ----
    conv1_nhwc<<<dim3(DIVUP(118*158, 512), 3, 128), 128>>>(
        x, (float*)q1p, cb[0], as, a1);

    // ---- convs 2-5: NHWC v8 (bit-identical DAG) ----
    conv_v8_nhwc<24, 36, 5, 2, 2><<<dim3(DIVUP(57*77, 256), 9, 128), 128>>>(
        a1, (float*)q2p, cb[1], as, a2, 118, 158, 57, 77);
    conv_v8_nhwc<36, 48, 5, 2, 2><<<dim3(DIVUP(27*37, 256), 12, 128), 128>>>(
        a2, (float*)q3p, cb[2], as, a3, 57, 77, 27, 37);
    conv_v8_nhwc<48, 64, 3, 1, 2><<<dim3(DIVUP(25*35, 256), 16, 128), 128>>>(
        a3, (float*)q4p, cb[3], as, a4, 27, 37, 25, 35);
    conv_v8_nhwc<64, 64, 3, 1, 2><<<dim3(DIVUP(23*33, 256), 16, 128), 128>>>(
        a4, (float*)q5p, cb[4], as, a5, 25, 35, 23, 33);

    // ---- FC layers ----
    k_fc1_part<<<dim3(64, FC1_SPLIT), 256>>>(a5, (float*)qf1tp, (float*)partp);
    k_fc1_epi<<<DIVUP(128*100, 256), 256>>>((float*)partp, fb[0], as, (float*)f1p);
    k_fc_small<<<DIVUP(128*50, 128), 128>>>((float*)f1p, (float*)qf2p, fb[1], as, (float*)f2p, 50, 100);
    k_fc_small<<<DIVUP(128*10, 128), 128>>>((float*)f2p, (float*)qf3p, fb[2], as, (float*)f3p, 10, 50);
    k_out<<<1, 128>>>((float*)f3p, (float*)qowp, obb, (float*)d_out);
}

// round 10
// speedup vs baseline: 2.5316x; 1.2691x over previous
#include <cuda_runtime.h>
#include <cstdint>

#define DIVUP(a,b) (((a)+(b)-1)/(b))

// ---------------- static scratch (no allocations allowed) ----------------
// Activations in NHWC layout: [n][h][w][c]
__device__ float g_a1[128*118*158*24];
__device__ float g_a2[128*57*77*36];
__device__ float g_a3[128*27*37*48];
__device__ float g_a4[128*25*35*64];
__device__ float g_a5[128*23*33*64];

__device__ float g_qw1[24*1*5*5];
__device__ float g_qw2[36*24*5*5];
__device__ float g_qw3[48*36*5*5];
__device__ float g_qw4[64*48*3*3];
__device__ float g_qw5[64*64*3*3];
__device__ float g_qfw1t[48576*100];     // fc1 weight: quantized, NHWC-permuted, [k][n]
__device__ float g_qfw2[50*100];
__device__ float g_qfw3[10*50];
__device__ float g_qow[10];

__device__ unsigned g_absmax[9];

#define FC1_SPLIT 32
__device__ float g_fc1part[FC1_SPLIT*128*100];
__device__ float g_f1[128*100];
__device__ float g_f2[128*50];
__device__ float g_f3[128*10];

// ---------------- weight fake-quant (exact fp32 semantics) ----------------
__global__ void k_reset_absmax() {
    if (threadIdx.x < 9) g_absmax[threadIdx.x] = 0u;
}

__global__ void k_absmax(const float* __restrict__ w, int n, int slot) {
    float m = 0.f;
    for (int i = blockIdx.x * blockDim.x + threadIdx.x; i < n; i += gridDim.x * blockDim.x)
        m = fmaxf(m, fabsf(w[i]));
#pragma unroll
    for (int off = 16; off > 0; off >>= 1)
        m = fmaxf(m, __shfl_xor_sync(0xffffffffu, m, off));
    __shared__ float sm[8];
    int lane = threadIdx.x & 31, wid = threadIdx.x >> 5;
    if (lane == 0) sm[wid] = m;
    __syncthreads();
    if (threadIdx.x == 0) {
        float mm = sm[0];
        for (int i = 1; i < (int)(blockDim.x >> 5); i++) mm = fmaxf(mm, sm[i]);
        atomicMax(&g_absmax[slot], __float_as_uint(mm)); // nonneg: uint order == float order
    }
}

__device__ __forceinline__ float quant_w(float w, float s) {
    float r = rintf(__fdiv_rn(w, s));   // jnp.round = RNE
    r = fminf(fmaxf(r, -7.f), 7.f);
    return r * s;
}

__global__ void k_quantw(const float* __restrict__ w, float* __restrict__ q, int n, int slot) {
    float s = __fdiv_rn(__uint_as_float(g_absmax[slot]), 7.0f);
    for (int i = blockIdx.x * blockDim.x + threadIdx.x; i < n; i += gridDim.x * blockDim.x)
        q[i] = quant_w(w[i], s);
}

// fc1 weight: quantize + permute NCHW-flat -> NHWC-flat + transpose to [k][n]
__global__ void k_quantw_fc1t(const float* __restrict__ w, float* __restrict__ wt) {
    float s = __fdiv_rn(__uint_as_float(g_absmax[5]), 7.0f);
    const int KD = 48576;                 // 64*23*33
    for (int i = blockIdx.x * blockDim.x + threadIdx.x; i < 100 * KD; i += gridDim.x * blockDim.x) {
        int nn = i / KD, f = i - nn * KD; // f = c*759 + hw (NCHW flat)
        int c = f / 759, hw = f - c * 759;
        int g = hw * 64 + c;              // NHWC flat
        wt[g * 100 + nn] = quant_w(w[i], s);
    }
}

// fp32 activation quant: identical to reference elementwise chain
__device__ __forceinline__ float qact(float v, float as) {
    v = fmaxf(v, 0.f);
    return fminf(rintf(__fdiv_rn(v, as)), 15.f) * as;
}

// ---------------- conv1: fused sequential (kh,kw) fp32 chain; NHWC output ----------------
__global__ void __launch_bounds__(128)
conv1_nhwc(const float* __restrict__ x, const float* __restrict__ w,
           const float* __restrict__ bias, const float* __restrict__ act_scale,
           float* __restrict__ y)
{
    constexpr int K = 5, S = 2, OCT = 8, P = 4;
    constexpr int Hin = 240, Win = 320, Hout = 118, Wout = 158, COUT = 24;
    __shared__ float sw[OCT * K * K];
    const int oc0 = blockIdx.y * OCT;
    const int n   = blockIdx.z;

    for (int i = threadIdx.x; i < OCT * K * K; i += 128)
        sw[i] = w[oc0 * K * K + i];
    __syncthreads();

    const int npix = Hout * Wout;
    const int p0 = blockIdx.x * (128 * P) + threadIdx.x;

    int xoff[P];
#pragma unroll
    for (int j = 0; j < P; j++) {
        int p = p0 + j * 128;
        int pp = (p < npix) ? p : 0;
        int oh = pp / Wout, ow = pp - oh * Wout;
        xoff[j] = oh * S * Win + ow * S;
    }

    float acc[OCT][P];
#pragma unroll
    for (int oc = 0; oc < OCT; oc++)
#pragma unroll
        for (int j = 0; j < P; j++) acc[oc][j] = 0.f;

    const float* xn = x + (size_t)n * Hin * Win;

#pragma unroll
    for (int kh = 0; kh < K; kh++) {
        const float* xr = xn + kh * Win;
#pragma unroll
        for (int kw = 0; kw < K; kw++) {
            float xv[P];
#pragma unroll
            for (int j = 0; j < P; j++)
                xv[j] = __ldg(xr + xoff[j] + kw);
#pragma unroll
            for (int oc = 0; oc < OCT; oc++) {
                float wv = sw[oc * K * K + kh * K + kw];
#pragma unroll
                for (int j = 0; j < P; j++)
                    acc[oc][j] = fmaf(xv[j], wv, acc[oc][j]);   // single fused chain
            }
        }
    }

    const float as = *act_scale;
    float bb[OCT];
#pragma unroll
    for (int oc = 0; oc < OCT; oc++) bb[oc] = bias[oc0 + oc];

#pragma unroll
    for (int j = 0; j < P; j++) {
        int p = p0 + j * 128;
        if (p < npix) {
            float* yp = y + ((size_t)n * npix + p) * COUT + oc0;
            float4 o0, o1;
            o0.x = qact(acc[0][j] + bb[0], as);
            o0.y = qact(acc[1][j] + bb[1], as);
            o0.z = qact(acc[2][j] + bb[2], as);
            o0.w = qact(acc[3][j] + bb[3], as);
            o1.x = qact(acc[4][j] + bb[4], as);
            o1.y = qact(acc[5][j] + bb[5], as);
            o1.z = qact(acc[6][j] + bb[6], as);
            o1.w = qact(acc[7][j] + bb[7], as);
            *reinterpret_cast<float4*>(yp)     = o0;
            *reinterpret_cast<float4*>(yp + 4) = o1;
        }
    }
}

// ---------------- convs 2-5: NHWC, 8-lane v8 DAG, wide-OCT (bit-identical per-output math) ----------------
// Per output, per (kh,kw): 8 fp32 lane accumulators over ci (lane = ci%8, running
// sum folded into lane 0), IC2 (l,l+4) combine + shuffle-halves tree, sequential
// scalar tail. OCT outputs per thread amortize each x-load over OCT*8 FMAs.
template<int CIN, int COUT, int K, int S, int OCT>
__global__ void __launch_bounds__(128)
conv_v8_nhwc(const float* __restrict__ x, const float* __restrict__ w,
             const float* __restrict__ bias, const float* __restrict__ act_scale,
             float* __restrict__ y, int Hin, int Win, int Hout, int Wout)
{
    constexpr int CKK = CIN * K * K;
    constexpr int WSZ = OCT * CKK;
    constexpr int C8  = CIN / 8;
    __shared__ __align__(16) float sw[WSZ];   // [oc][kh][kw][ci]
    const int oc0 = blockIdx.y * OCT;
    const int n   = blockIdx.z;

    for (int i = threadIdx.x; i < WSZ; i += 128) {
        int oc = i / CKK;
        int rem = i - oc * CKK;
        int kh = rem / (K * CIN);
        rem -= kh * (K * CIN);
        int kw = rem / CIN;
        int ci = rem - kw * CIN;
        sw[i] = w[((oc0 + oc) * CIN + ci) * (K * K) + kh * K + kw];
    }
    __syncthreads();

    const int npix = Hout * Wout;
    const int p = blockIdx.x * 128 + threadIdx.x;
    const int pp = (p < npix) ? p : 0;
    const int oh = pp / Wout, ow = pp - oh * Wout;
    const int xbase = (oh * S * Win + ow * S) * CIN;

    float s[OCT];
#pragma unroll
    for (int oc = 0; oc < OCT; oc++) s[oc] = 0.f;

    const float* xn = x + (size_t)n * Hin * Win * CIN;

#pragma unroll
    for (int kh = 0; kh < K; kh++) {
#pragma unroll
        for (int kw = 0; kw < K; kw++) {
            const int off = (kh * Win + kw) * CIN;
            const int woff = (kh * K + kw) * CIN;

            float v[OCT][8];
#pragma unroll
            for (int oc = 0; oc < OCT; oc++) {
                v[oc][0] = s[oc];
#pragma unroll
                for (int l = 1; l < 8; l++) v[oc][l] = 0.f;
            }

            const float4* xp = reinterpret_cast<const float4*>(xn + xbase + off);
#pragma unroll
            for (int c = 0; c < C8; c++) {
                float4 xa = __ldg(xp + 2 * c);
                float4 xb = __ldg(xp + 2 * c + 1);
#pragma unroll
                for (int oc = 0; oc < OCT; oc++) {
                    const float4* wp = reinterpret_cast<const float4*>(sw + oc * CKK + woff);
                    float4 wa = wp[2 * c], wb = wp[2 * c + 1];
                    v[oc][0] = fmaf(xa.x, wa.x, v[oc][0]);
                    v[oc][1] = fmaf(xa.y, wa.y, v[oc][1]);
                    v[oc][2] = fmaf(xa.z, wa.z, v[oc][2]);
                    v[oc][3] = fmaf(xa.w, wa.w, v[oc][3]);
                    v[oc][4] = fmaf(xb.x, wb.x, v[oc][4]);
                    v[oc][5] = fmaf(xb.y, wb.y, v[oc][5]);
                    v[oc][6] = fmaf(xb.z, wb.z, v[oc][6]);
                    v[oc][7] = fmaf(xb.w, wb.w, v[oc][7]);
                }
            }

            // reduce: IC2 combine (l, l+4) then shuffle-halves tree
#pragma unroll
            for (int oc = 0; oc < OCT; oc++) {
                float h0 = __fadd_rn(v[oc][0], v[oc][4]);
                float h1 = __fadd_rn(v[oc][1], v[oc][5]);
                float h2 = __fadd_rn(v[oc][2], v[oc][6]);
                float h3 = __fadd_rn(v[oc][3], v[oc][7]);
                s[oc] = __fadd_rn(__fadd_rn(h0, h2), __fadd_rn(h1, h3));
            }

            // scalar tail (ci = 8*C8 .. CIN-1), sequential
#pragma unroll
            for (int ci = 8 * C8; ci < CIN; ci++) {
                float xt = __ldg(xn + xbase + off + ci);
#pragma unroll
                for (int oc = 0; oc < OCT; oc++)
                    s[oc] = fmaf(xt, sw[oc * CKK + woff + ci], s[oc]);
            }
        }
    }

    if (p < npix) {
        const float as = *act_scale;
        float* yp = y + ((size_t)n * npix + p) * COUT + oc0;
#pragma unroll
        for (int oq = 0; oq < OCT / 4; oq++) {
            float4 o;
            o.x = qact(s[oq * 4 + 0] + bias[oc0 + oq * 4 + 0], as);
            o.y = qact(s[oq * 4 + 1] + bias[oc0 + oq * 4 + 1], as);
            o.z = qact(s[oq * 4 + 2] + bias[oc0 + oq * 4 + 2], as);
            o.w = qact(s[oq * 4 + 3] + bias[oc0 + oq * 4 + 3], as);
            *reinterpret_cast<float4*>(yp + oq * 4) = o;
        }
    }
}

// ---------------- FC1: fp32 split-K (FC layers proven flip-free) ----------------
__global__ void __launch_bounds__(256)
k_fc1_part(const float* __restrict__ A, const float* __restrict__ Wt,
           float* __restrict__ part)
{
    constexpr int KD = 48576;
    constexpr int LEN = KD / FC1_SPLIT;   // 1518
    __shared__ float sA[2][LEN];
    const int tid = threadIdx.x;
    const int m0  = blockIdx.x * 2;
    const int s   = blockIdx.y;
    const int k0  = s * LEN;

    for (int i = tid; i < 2 * LEN; i += 256) {
        int r = i / LEN, k = i - r * LEN;
        sA[r][k] = A[(size_t)(m0 + r) * KD + k0 + k];
    }
    __syncthreads();

    if (tid < 200) {
        int ml = tid / 100, nn = tid - ml * 100;
        const float* wp = Wt + (size_t)k0 * 100 + nn;
        float acc = 0.f;
#pragma unroll 6
        for (int k = 0; k < LEN; k++)
            acc = fmaf(sA[ml][k], __ldg(wp + (size_t)k * 100), acc);
        part[(s * 128 + m0 + ml) * 100 + nn] = acc;
    }
}

__global__ void k_fc1_epi(const float* __restrict__ part,
                          const float* __restrict__ bias,
                          const float* __restrict__ act_scale,
                          float* __restrict__ out)
{
    int idx = blockIdx.x * blockDim.x + threadIdx.x;
    if (idx >= 128 * 100) return;
    float v = 0.f;
    for (int s = 0; s < FC1_SPLIT; s++) v += part[s * 12800 + idx];  // fixed order
    int nn = idx % 100;
    float f = v + bias[nn];
    out[idx] = qact(f, *act_scale);
}

// ---------------- small FC layers, fp64 (tiny; keep exact) ----------------
__global__ void k_fc_small(const float* __restrict__ A, const float* __restrict__ W,
                           const float* __restrict__ bias, const float* __restrict__ act_scale,
                           float* __restrict__ C, int N, int Kd)
{
    int idx = blockIdx.x * blockDim.x + threadIdx.x;
    if (idx >= 128 * N) return;
    int m = idx / N, nn = idx - m * N;
    const float* a = A + m * Kd;
    const float* w = W + nn * Kd;
    double acc = 0.0;
    for (int k = 0; k < Kd; k++) acc = fma((double)__ldg(a + k), (double)__ldg(w + k), acc);
    float f = (float)acc + bias[nn];
    C[idx] = qact(f, *act_scale);
}

__global__ void k_out(const float* __restrict__ f3, const float* __restrict__ ow_q,
                      const float* __restrict__ ob, float* __restrict__ out)
{
    int m = blockIdx.x * blockDim.x + threadIdx.x;
    if (m >= 128) return;
    double acc = 0.0;
#pragma unroll
    for (int k = 0; k < 10; k++) acc = fma((double)f3[m * 10 + k], (double)ow_q[k], acc);
    out[m] = (float)acc + ob[0];
}

// ---------------- host ----------------
extern "C" void kernel_launch(void* const* d_in, const int* in_sizes, int n_in,
                              void* d_out, int out_size)
{
    const float* x   = (const float*)d_in[0];
    const float* cw[5] = {(const float*)d_in[1], (const float*)d_in[3], (const float*)d_in[5],
                          (const float*)d_in[7], (const float*)d_in[9]};
    const float* cb[5] = {(const float*)d_in[2], (const float*)d_in[4], (const float*)d_in[6],
                          (const float*)d_in[8], (const float*)d_in[10]};
    const float* fw[3] = {(const float*)d_in[11], (const float*)d_in[13], (const float*)d_in[15]};
    const float* fb[3] = {(const float*)d_in[12], (const float*)d_in[14], (const float*)d_in[16]};
    const float* oww = (const float*)d_in[17];
    const float* obb = (const float*)d_in[18];
    const float* as  = (const float*)d_in[19];

    void *a1p, *a2p, *a3p, *a4p, *a5p;
    void *q1p, *q2p, *q3p, *q4p, *q5p, *qf1tp, *qf2p, *qf3p, *qowp;
    void *partp, *f1p, *f2p, *f3p;
    cudaGetSymbolAddress(&a1p, g_a1);   cudaGetSymbolAddress(&a2p, g_a2);
    cudaGetSymbolAddress(&a3p, g_a3);   cudaGetSymbolAddress(&a4p, g_a4);
    cudaGetSymbolAddress(&a5p, g_a5);
    cudaGetSymbolAddress(&q1p, g_qw1);  cudaGetSymbolAddress(&q2p, g_qw2);
    cudaGetSymbolAddress(&q3p, g_qw3);  cudaGetSymbolAddress(&q4p, g_qw4);
    cudaGetSymbolAddress(&q5p, g_qw5);
    cudaGetSymbolAddress(&qf1tp, g_qfw1t); cudaGetSymbolAddress(&qf2p, g_qfw2);
    cudaGetSymbolAddress(&qf3p, g_qfw3);   cudaGetSymbolAddress(&qowp, g_qow);
    cudaGetSymbolAddress(&partp, g_fc1part);
    cudaGetSymbolAddress(&f1p, g_f1);   cudaGetSymbolAddress(&f2p, g_f2);
    cudaGetSymbolAddress(&f3p, g_f3);

    float* a1 = (float*)a1p; float* a2 = (float*)a2p; float* a3 = (float*)a3p;
    float* a4 = (float*)a4p; float* a5 = (float*)a5p;

    // ---- weight quantization ----
    k_reset_absmax<<<1, 32>>>();

    const float* qsrc[9] = {cw[0], cw[1], cw[2], cw[3], cw[4], fw[0], fw[1], fw[2], oww};
    const int qn[9] = {24*1*5*5, 36*24*5*5, 48*36*5*5, 64*48*3*3, 64*64*3*3,
                       100*48576, 50*100, 10*50, 10};
    for (int i = 0; i < 9; i++) {
        int blocks = DIVUP(qn[i], 256); if (blocks > 512) blocks = 512;
        k_absmax<<<blocks, 256>>>(qsrc[i], qn[i], i);
    }
    k_quantw<<<DIVUP(qn[0],256), 256>>>(qsrc[0], (float*)q1p, qn[0], 0);
    k_quantw<<<DIVUP(qn[1],256), 256>>>(qsrc[1], (float*)q2p, qn[1], 1);
    k_quantw<<<DIVUP(qn[2],256), 256>>>(qsrc[2], (float*)q3p, qn[2], 2);
    k_quantw<<<DIVUP(qn[3],256), 256>>>(qsrc[3], (float*)q4p, qn[3], 3);
    k_quantw<<<DIVUP(qn[4],256), 256>>>(qsrc[4], (float*)q5p, qn[4], 4);
    k_quantw_fc1t<<<4096, 256>>>(qsrc[5], (float*)qf1tp);
    k_quantw<<<DIVUP(qn[6],256), 256>>>(qsrc[6], (float*)qf2p, qn[6], 6);
    k_quantw<<<DIVUP(qn[7],256), 256>>>(qsrc[7], (float*)qf3p, qn[7], 7);
    k_quantw<<<1, 32>>>(qsrc[8], (float*)qowp, qn[8], 8);

    // ---- conv1: fused sequential chain, NHWC out ----
    conv1_nhwc<<<dim3(DIVUP(118*158, 512), 3, 128), 128>>>(
        x, (float*)q1p, cb[0], as, a1);

    // ---- convs 2-5: NHWC v8, wide-OCT (bit-identical per-output DAG) ----
    conv_v8_nhwc<24, 36, 5, 2, 12><<<dim3(DIVUP(57*77, 128), 3, 128), 128>>>(
        a1, (float*)q2p, cb[1], as, a2, 118, 158, 57, 77);
    conv_v8_nhwc<36, 48, 5, 2, 16><<<dim3(DIVUP(27*37, 128), 3, 128), 128>>>(
        a2, (float*)q3p, cb[2], as, a3, 57, 77, 27, 37);
    conv_v8_nhwc<48, 64, 3, 1, 16><<<dim3(DIVUP(25*35, 128), 4, 128), 128>>>(
        a3, (float*)q4p, cb[3], as, a4, 27, 37, 25, 35);
    conv_v8_nhwc<64, 64, 3, 1, 16><<<dim3(DIVUP(23*33, 128), 4, 128), 128>>>(
        a4, (float*)q5p, cb[4], as, a5, 25, 35, 23, 33);

    // ---- FC layers ----
    k_fc1_part<<<dim3(64, FC1_SPLIT), 256>>>(a5, (float*)qf1tp, (float*)partp);
    k_fc1_epi<<<DIVUP(128*100, 256), 256>>>((float*)partp, fb[0], as, (float*)f1p);
    k_fc_small<<<DIVUP(128*50, 128), 128>>>((float*)f1p, (float*)qf2p, fb[1], as, (float*)f2p, 50, 100);
    k_fc_small<<<DIVUP(128*10, 128), 128>>>((float*)f2p, (float*)qf3p, fb[2], as, (float*)f3p, 10, 50);
    k_out<<<1, 128>>>((float*)f3p, (float*)qowp, obb, (float*)d_out);
}